// round 2
// baseline (speedup 1.0000x reference)
#include <cuda_runtime.h>

// DiceFromLabelsLoss: counts per (batch, class in 1..9) of
//   P = #(yp==c), T = #(yt==c), I = #(yp==c && yt==c)
// then loss = 1 - sum_n sum_c [denom>0] * (T/sumT/NB) * (2I/(P+T))
//
// Hot loop: warp-ballot counting, register accumulators, no atomics per element.

#define NB 4
#define NC 9  // classes 1..9 (class 0 = background is ignored entirely)

__device__ unsigned int g_hist[NB][3][NC];  // [batch][{P,T,I}][class-1]

__global__ void dice_zero_kernel() {
    int i = threadIdx.x;
    if (i < NB * 3 * NC) (&g_hist[0][0][0])[i] = 0u;
}

__global__ __launch_bounds__(512) void dice_hist_kernel(
    const int4* __restrict__ yp, const int4* __restrict__ yt, int n4_per_batch) {
    const int n = blockIdx.y;
    const int4* p = yp + (size_t)n * n4_per_batch;
    const int4* t = yt + (size_t)n * n4_per_batch;

    unsigned sP[NC], sT[NC], sI[NC];
#pragma unroll
    for (int c = 0; c < NC; c++) { sP[c] = 0u; sT[c] = 0u; sI[c] = 0u; }

    const int stride = blockDim.x * gridDim.x;
    // n4_per_batch (1,024,000) and stride are both multiples of 32, so every
    // warp's lanes share identical trip counts -> full-mask ballots are safe.
    for (int i = blockIdx.x * blockDim.x + threadIdx.x; i < n4_per_batch; i += stride) {
        const int4 a = p[i];
        const int4 b = t[i];
        const int va[4] = {a.x, a.y, a.z, a.w};
        const int vb[4] = {b.x, b.y, b.z, b.w};
#pragma unroll
        for (int j = 0; j < 4; j++) {
#pragma unroll
            for (int c = 1; c <= NC; c++) {
                unsigned bp = __ballot_sync(0xFFFFFFFFu, va[j] == c);
                unsigned bt = __ballot_sync(0xFFFFFFFFu, vb[j] == c);
                sP[c - 1] += (unsigned)__popc(bp);
                sT[c - 1] += (unsigned)__popc(bt);
                sI[c - 1] += (unsigned)__popc(bp & bt);
            }
        }
    }

    // All 32 lanes hold identical accumulator values; lane 0 of each warp
    // contributes once into a block-shared histogram, then 27 threads flush
    // to global with atomics.
    __shared__ unsigned sh[3 * NC];
    if (threadIdx.x < 3 * NC) sh[threadIdx.x] = 0u;
    __syncthreads();
    if ((threadIdx.x & 31) == 0) {
#pragma unroll
        for (int c = 0; c < NC; c++) {
            atomicAdd(&sh[c], sP[c]);
            atomicAdd(&sh[NC + c], sT[c]);
            atomicAdd(&sh[2 * NC + c], sI[c]);
        }
    }
    __syncthreads();
    if (threadIdx.x < 3 * NC)
        atomicAdd(&(&g_hist[n][0][0])[threadIdx.x], sh[threadIdx.x]);
}

__global__ void dice_finalize_kernel(float* __restrict__ out) {
    if (threadIdx.x == 0) {
        float acc = 0.0f;
#pragma unroll
        for (int n = 0; n < NB; n++) {
            float sumT = 0.0f;
#pragma unroll
            for (int c = 0; c < NC; c++) sumT += (float)g_hist[n][1][c];
#pragma unroll
            for (int c = 0; c < NC; c++) {
                const float P = (float)g_hist[n][0][c];
                const float T = (float)g_hist[n][1][c];
                const float I = (float)g_hist[n][2][c];
                const float d = P + T;
                if (d > 0.0f) {
                    const float dice = 2.0f * I / d;
                    const float w = T / sumT * (1.0f / (float)NB);
                    acc += w * dice;
                }
            }
        }
        out[0] = 1.0f - acc;
    }
}

extern "C" void kernel_launch(void* const* d_in, const int* in_sizes, int n_in,
                              void* d_out, int out_size) {
    const int4* yp = (const int4*)d_in[0];
    const int4* yt = (const int4*)d_in[1];
    const int total = in_sizes[0];        // 16,384,000 elements
    const int per_batch = total / NB;     // 4,096,000
    const int n4 = per_batch / 4;         // 1,024,000 int4 per batch

    dice_zero_kernel<<<1, 128>>>();
    dim3 grid(74, NB);                    // 296 blocks, 512 threads each
    dice_hist_kernel<<<grid, 512>>>(yp, yt, n4);
    dice_finalize_kernel<<<1, 32>>>((float*)d_out);
}

// round 3
// speedup vs baseline: 1.0054x; 1.0054x over previous
#include <cuda_runtime.h>

// DiceFromLabelsLoss: counts per (batch, class in 1..9) of
//   P = #(yp==c), T = #(yt==c), I = #(yp==c && yt==c)
// then loss = 1 - sum_n sum_c [denom>0] * (T/sumT/NB) * (2I/(P+T))
//
// Hot loop: warp-ballot counting, register accumulators, no atomics per element.

#define NB 4
#define NC 9  // classes 1..9 (class 0 = background is ignored entirely)

__device__ unsigned int g_hist[NB][3][NC];  // [batch][{P,T,I}][class-1]

__global__ void dice_zero_kernel() {
    int i = threadIdx.x;
    if (i < NB * 3 * NC) (&g_hist[0][0][0])[i] = 0u;
}

__global__ __launch_bounds__(512) void dice_hist_kernel(
    const int4* __restrict__ yp, const int4* __restrict__ yt, int n4_per_batch) {
    const int n = blockIdx.y;
    const int4* p = yp + (size_t)n * n4_per_batch;
    const int4* t = yt + (size_t)n * n4_per_batch;

    unsigned sP[NC], sT[NC], sI[NC];
#pragma unroll
    for (int c = 0; c < NC; c++) { sP[c] = 0u; sT[c] = 0u; sI[c] = 0u; }

    const int stride = blockDim.x * gridDim.x;
    // n4_per_batch (1,024,000) and stride are both multiples of 32, so every
    // warp's lanes share identical trip counts -> full-mask ballots are safe.
    for (int i = blockIdx.x * blockDim.x + threadIdx.x; i < n4_per_batch; i += stride) {
        const int4 a = p[i];
        const int4 b = t[i];
        const int va[4] = {a.x, a.y, a.z, a.w};
        const int vb[4] = {b.x, b.y, b.z, b.w};
#pragma unroll
        for (int j = 0; j < 4; j++) {
#pragma unroll
            for (int c = 1; c <= NC; c++) {
                unsigned bp = __ballot_sync(0xFFFFFFFFu, va[j] == c);
                unsigned bt = __ballot_sync(0xFFFFFFFFu, vb[j] == c);
                sP[c - 1] += (unsigned)__popc(bp);
                sT[c - 1] += (unsigned)__popc(bt);
                sI[c - 1] += (unsigned)__popc(bp & bt);
            }
        }
    }

    // All 32 lanes hold identical accumulator values; lane 0 of each warp
    // contributes once into a block-shared histogram, then 27 threads flush
    // to global with atomics.
    __shared__ unsigned sh[3 * NC];
    if (threadIdx.x < 3 * NC) sh[threadIdx.x] = 0u;
    __syncthreads();
    if ((threadIdx.x & 31) == 0) {
#pragma unroll
        for (int c = 0; c < NC; c++) {
            atomicAdd(&sh[c], sP[c]);
            atomicAdd(&sh[NC + c], sT[c]);
            atomicAdd(&sh[2 * NC + c], sI[c]);
        }
    }
    __syncthreads();
    if (threadIdx.x < 3 * NC)
        atomicAdd(&(&g_hist[n][0][0])[threadIdx.x], sh[threadIdx.x]);
}

__global__ void dice_finalize_kernel(float* __restrict__ out) {
    if (threadIdx.x == 0) {
        float acc = 0.0f;
#pragma unroll
        for (int n = 0; n < NB; n++) {
            float sumT = 0.0f;
#pragma unroll
            for (int c = 0; c < NC; c++) sumT += (float)g_hist[n][1][c];
#pragma unroll
            for (int c = 0; c < NC; c++) {
                const float P = (float)g_hist[n][0][c];
                const float T = (float)g_hist[n][1][c];
                const float I = (float)g_hist[n][2][c];
                const float d = P + T;
                if (d > 0.0f) {
                    const float dice = 2.0f * I / d;
                    const float w = T / sumT * (1.0f / (float)NB);
                    acc += w * dice;
                }
            }
        }
        out[0] = 1.0f - acc;
    }
}

extern "C" void kernel_launch(void* const* d_in, const int* in_sizes, int n_in,
                              void* d_out, int out_size) {
    const int4* yp = (const int4*)d_in[0];
    const int4* yt = (const int4*)d_in[1];
    const int total = in_sizes[0];        // 16,384,000 elements
    const int per_batch = total / NB;     // 4,096,000
    const int n4 = per_batch / 4;         // 1,024,000 int4 per batch

    dice_zero_kernel<<<1, 128>>>();
    dim3 grid(74, NB);                    // 296 blocks, 512 threads each
    dice_hist_kernel<<<grid, 512>>>(yp, yt, n4);
    dice_finalize_kernel<<<1, 32>>>((float*)d_out);
}

// round 4
// speedup vs baseline: 3.1770x; 3.1599x over previous
#include <cuda_runtime.h>

// DiceFromLabelsLoss — single fused kernel.
// Per (batch, class c in 1..9): P=#(yp==c), T=#(yt==c), I=#(yp==c && yt==c).
// loss = 1 - sum_n sum_c [P+T>0] * (T / sumT / NB) * (2I/(P+T))
//
// Hot loop: packed 64-bit histogram accumulators, 10 classes x 6-bit fields,
// direct shift-add per element (no per-class ballots, no per-element atomics).
// Flushed to 32-bit per-class registers every 15 int4s (<=60 increments per
// field, capacity 63). Last finished block computes the scalar loss and
// re-zeroes the device-global state so graph replays stay deterministic.

#define NB 4
#define NC 9

__device__ unsigned g_hist[NB][3][NC];  // [batch][{P,T,I}][class-1]
__device__ unsigned g_done;

__global__ __launch_bounds__(512, 2) void dice_fused_kernel(
    const int4* __restrict__ yp, const int4* __restrict__ yt,
    int n4_per_batch, int nblocks_total, float* __restrict__ out) {
    const int n = blockIdx.y;
    const int4* __restrict__ p = yp + (size_t)n * n4_per_batch;
    const int4* __restrict__ t = yt + (size_t)n * n4_per_batch;
    const int stride = blockDim.x * gridDim.x;

    unsigned P[NC], T[NC], I[NC];
#pragma unroll
    for (int c = 0; c < NC; c++) { P[c] = 0u; T[c] = 0u; I[c] = 0u; }

    __shared__ unsigned sh[3 * NC];
    __shared__ unsigned s_last;
    if (threadIdx.x < 3 * NC) sh[threadIdx.x] = 0u;
    __syncthreads();

    int i = blockIdx.x * blockDim.x + threadIdx.x;
    while (i < n4_per_batch) {
        unsigned long long aP = 0ull, aT = 0ull, aI = 0ull;
#pragma unroll
        for (int k = 0; k < 15; k++) {
            if (i < n4_per_batch) {
                const int4 a = p[i];
                const int4 b = t[i];
                const int va[4] = {a.x, a.y, a.z, a.w};
                const int vb[4] = {b.x, b.y, b.z, b.w};
#pragma unroll
                for (int j = 0; j < 4; j++) {
                    const unsigned long long pa = 1ull << (6 * va[j]);
                    aP += pa;
                    aT += 1ull << (6 * vb[j]);
                    if (va[j] == vb[j]) aI += pa;
                }
            }
            i += stride;
        }
        // Field capacity: <= 15*4 = 60 increments per accumulator, < 63.
#pragma unroll
        for (int c = 1; c <= NC; c++) {
            P[c - 1] += (unsigned)(aP >> (6 * c)) & 63u;
            T[c - 1] += (unsigned)(aT >> (6 * c)) & 63u;
            I[c - 1] += (unsigned)(aI >> (6 * c)) & 63u;
        }
    }

    // Warp butterfly reduce, then one smem atomic per warp per counter.
#pragma unroll
    for (int c = 0; c < NC; c++) {
#pragma unroll
        for (int off = 16; off; off >>= 1) {
            P[c] += __shfl_xor_sync(0xFFFFFFFFu, P[c], off);
            T[c] += __shfl_xor_sync(0xFFFFFFFFu, T[c], off);
            I[c] += __shfl_xor_sync(0xFFFFFFFFu, I[c], off);
        }
    }
    if ((threadIdx.x & 31) == 0) {
#pragma unroll
        for (int c = 0; c < NC; c++) {
            atomicAdd(&sh[c], P[c]);
            atomicAdd(&sh[NC + c], T[c]);
            atomicAdd(&sh[2 * NC + c], I[c]);
        }
    }
    __syncthreads();
    if (threadIdx.x < 3 * NC)
        atomicAdd(&(&g_hist[n][0][0])[threadIdx.x], sh[threadIdx.x]);

    // Last-block-done finalize.
    __threadfence();
    if (threadIdx.x == 0) {
        unsigned ticket = atomicAdd(&g_done, 1u);
        s_last = (ticket == (unsigned)(nblocks_total - 1)) ? 1u : 0u;
    }
    __syncthreads();
    if (s_last) {
        if (threadIdx.x == 0) {
            __threadfence();
            float acc = 0.0f;
#pragma unroll
            for (int b = 0; b < NB; b++) {
                float sumT = 0.0f;
#pragma unroll
                for (int c = 0; c < NC; c++) sumT += (float)g_hist[b][1][c];
                const float winv = (sumT > 0.0f) ? 1.0f / (sumT * (float)NB) : 0.0f;
#pragma unroll
                for (int c = 0; c < NC; c++) {
                    const float Pp = (float)g_hist[b][0][c];
                    const float Tt = (float)g_hist[b][1][c];
                    const float Ii = (float)g_hist[b][2][c];
                    const float d = Pp + Tt;
                    if (d > 0.0f) acc += (Tt * winv) * (2.0f * Ii / d);
                }
            }
            out[0] = 1.0f - acc;
        }
        __syncthreads();  // finalize read complete before re-zeroing
        if (threadIdx.x < NB * 3 * NC) (&g_hist[0][0][0])[threadIdx.x] = 0u;
        if (threadIdx.x == 0) g_done = 0u;
    }
}

extern "C" void kernel_launch(void* const* d_in, const int* in_sizes, int n_in,
                              void* d_out, int out_size) {
    const int4* yp = (const int4*)d_in[0];
    const int4* yt = (const int4*)d_in[1];
    const int total = in_sizes[0];     // 16,384,000
    const int per_batch = total / NB;  // 4,096,000
    const int n4 = per_batch / 4;      // 1,024,000 int4 per batch

    dim3 grid(74, NB);  // 296 blocks x 512 threads, 2 CTAs/SM
    dice_fused_kernel<<<grid, 512>>>(yp, yt, n4, 74 * NB, (float*)d_out);
}